// round 1
// baseline (speedup 1.0000x reference)
#include <cuda_runtime.h>
#include <math.h>

#define B_    8
#define D_    512
#define L_    1024
#define NPOS  8192          // B_*L_
#define KCB   8192          // number of codes
#define EDIM  512
#define SEMD  256
#define NQ    4194304       // B_*D_*L_  (z_q element count)

typedef unsigned long long ull;

// ---------------- scratch (static device globals; no allocation) ----------------
static __device__ float g_Zn[NPOS * EDIM];     // normalized queries, (n, e) row-major
static __device__ float g_En[KCB * EDIM];      // normalized codes,   (k, e) row-major
static __device__ float g_psum[8][NPOS];       // partial sumsq of z per 64-d segment
static __device__ float g_invk[NPOS], g_invg[NPOS];
static __device__ float g_akd[NPOS],  g_agan[NPOS];
static __device__ float g_bkd[KCB],   g_bgan[KCB];
static __device__ float g_pSkd[2][NPOS], g_pSgan[2][NPOS], g_pBv[2][NPOS];
static __device__ int   g_pBi[2][NPOS];
static __device__ int   g_idx[NPOS];

// ---------------- small helpers ----------------
__device__ __forceinline__ ull ffma2(ull a, ull b, ull c) {
    ull d;
    asm("fma.rn.f32x2 %0, %1, %2, %3;" : "=l"(d) : "l"(a), "l"(b), "l"(c));
    return d;
}
__device__ __forceinline__ void upk(ull v, float &lo, float &hi) {
    asm("mov.b64 {%0, %1}, %2;" : "=f"(lo), "=f"(hi) : "l"(v));
}
__device__ __forceinline__ float wsum(float s) {
#pragma unroll
    for (int o = 16; o > 0; o >>= 1) s += __shfl_xor_sync(0xffffffffu, s, o);
    return s;
}

// ---------------- 1. normalize embeddings (one warp per code row) ----------------
__global__ void k_emb(const float* __restrict__ ekd, const float* __restrict__ egan) {
    int w    = threadIdx.x >> 5;
    int lane = threadIdx.x & 31;
    int k    = blockIdx.x * 8 + w;
    if (k >= KCB) return;

    // kd half
    {
        const float* p = ekd + (size_t)k * SEMD;
        float v[8]; float s = 0.f;
#pragma unroll
        for (int j = 0; j < 8; ++j) { v[j] = p[lane + j * 32]; s += v[j] * v[j]; }
        s = wsum(s);
        float inv = 1.f / fmaxf(sqrtf(s), 1e-12f);
        float t = 0.f;
#pragma unroll
        for (int j = 0; j < 8; ++j) {
            float nv = v[j] * inv;
            g_En[(size_t)k * EDIM + lane + j * 32] = nv;
            t += nv * nv;
        }
        t = wsum(t);
        if (lane == 0) g_bkd[k] = t;
    }
    // gan half
    {
        const float* p = egan + (size_t)k * SEMD;
        float v[8]; float s = 0.f;
#pragma unroll
        for (int j = 0; j < 8; ++j) { v[j] = p[lane + j * 32]; s += v[j] * v[j]; }
        s = wsum(s);
        float inv = 1.f / fmaxf(sqrtf(s), 1e-12f);
        float t = 0.f;
#pragma unroll
        for (int j = 0; j < 8; ++j) {
            float nv = v[j] * inv;
            g_En[(size_t)k * EDIM + SEMD + lane + j * 32] = nv;
            t += nv * nv;
        }
        t = wsum(t);
        if (lane == 0) g_bgan[k] = t;
    }
}

// ---------------- 2. z sum-of-squares partials (coalesced over l) ----------------
__global__ void k_zsumsq(const float* __restrict__ z) {
    int l   = blockIdx.x * 256 + threadIdx.x;   // grid.x = 4
    int b   = blockIdx.y;                       // grid.y = 8
    int seg = blockIdx.z;                       // grid.z = 8 (64 d each)
    const float* p = z + (size_t)b * D_ * L_ + (size_t)seg * 64 * L_ + l;
    float s = 0.f;
#pragma unroll 8
    for (int d = 0; d < 64; ++d) { float v = p[(size_t)d * L_]; s += v * v; }
    g_psum[seg][b * L_ + l] = s;
}

// ---------------- 3. finalize norms ----------------
__global__ void k_zfinal() {
    int n = blockIdx.x * 256 + threadIdx.x;
    float s = g_psum[0][n]; s += g_psum[1][n]; s += g_psum[2][n]; s += g_psum[3][n];
    float inv = 1.f / fmaxf(sqrtf(s), 1e-12f);
    g_invk[n] = inv;
    g_akd[n]  = s * inv * inv;
    float s2 = g_psum[4][n]; s2 += g_psum[5][n]; s2 += g_psum[6][n]; s2 += g_psum[7][n];
    float inv2 = 1.f / fmaxf(sqrtf(s2), 1e-12f);
    g_invg[n] = inv2;
    g_agan[n] = s2 * inv2 * inv2;
}

// ---------------- 4. transpose + normalize z into Zn (n, e) ----------------
__global__ void k_ztrans(const float* __restrict__ z) {
    __shared__ float s[32][33];
    int d0 = blockIdx.x * 32;   // grid.x = 16
    int l0 = blockIdx.y * 32;   // grid.y = 32
    int b  = blockIdx.z;        // grid.z = 8
    int tx = threadIdx.x;       // 32
    int ty2 = threadIdx.y;      // 8
#pragma unroll
    for (int q = 0; q < 4; ++q) {
        int dy = ty2 * 4 + q;
        s[dy][tx] = z[((size_t)b * D_ + d0 + dy) * L_ + l0 + tx];
    }
    __syncthreads();
    bool kdh = (d0 < SEMD);
#pragma unroll
    for (int q = 0; q < 4; ++q) {
        int lr = ty2 * 4 + q;
        int n  = b * L_ + l0 + lr;
        float inv = kdh ? g_invk[n] : g_invg[n];
        g_Zn[(size_t)n * EDIM + d0 + tx] = s[tx][lr] * inv;
    }
}

// ---------------- 5. fused GEMM + distance stats + argmin (split-K=2) ----------------
__global__ void __launch_bounds__(256, 2) k_gemm() {
    const int rt    = blockIdx.x;     // 0..127 row tile
    const int split = blockIdx.y;     // 0..1
    const int row0  = rt * 64;
    const int kbase = split * 4096;
    const int tid = threadIdx.x;
    const int tx = tid & 15, ty = tid >> 4;
    const int ty4 = ty * 4;
    const int lr = tid >> 2;                 // loader row 0..63
    const int lc = (tid & 3) * 8;            // loader col base {0,8,16,24}

    union Sm {
        struct { float2 A[64][33]; float B[32][66]; } t;   // A duplicated pairs
        struct { float S1[64][17]; float S2[64][17]; float Bv[64][17]; int Bi[64][17]; } r;
    };
    __shared__ Sm sm;

    ull acck[4][2], accg[4][2];
#pragma unroll
    for (int i = 0; i < 4; ++i) { acck[i][0] = 0ull; acck[i][1] = 0ull; accg[i][0] = 0ull; accg[i][1] = 0ull; }

    float Skd[4]  = {0.f, 0.f, 0.f, 0.f};
    float Sgan[4] = {0.f, 0.f, 0.f, 0.f};
    float bestv[4]; int besti[4];
    float ak[4], ag[4];
#pragma unroll
    for (int i = 0; i < 4; ++i) {
        ak[i] = g_akd[row0 + ty4 + i];
        ag[i] = g_agan[row0 + ty4 + i];
        bestv[i] = 3.402823466e38f; besti[i] = 0;
    }

    const float* Abase = g_Zn + (size_t)(row0 + lr) * EDIM + lc;

    float4 pa0, pa1, pb0, pb1;
    auto prefetch = [&](int it) {
        int kt = it >> 4;
        int db = ((it >> 3) & 1) * 256 + (it & 7) * 32;
        const float* Ap = Abase + db;
        const float* Bp = g_En + (size_t)(kbase + kt * 64 + lr) * EDIM + lc + db;
        pa0 = *(const float4*)(Ap);
        pa1 = *(const float4*)(Ap + 4);
        pb0 = *(const float4*)(Bp);
        pb1 = *(const float4*)(Bp + 4);
    };

    auto compute_phase = [&](ull (&acc)[4][2]) {
#pragma unroll
        for (int dd = 0; dd < 32; ++dd) {
            ull A0 = *(const ull*)&sm.t.A[ty4 + 0][dd];
            ull A1 = *(const ull*)&sm.t.A[ty4 + 1][dd];
            ull A2 = *(const ull*)&sm.t.A[ty4 + 2][dd];
            ull A3 = *(const ull*)&sm.t.A[ty4 + 3][dd];
            ull B0 = *(const ull*)&sm.t.B[dd][tx * 4];
            ull B1 = *(const ull*)&sm.t.B[dd][tx * 4 + 2];
            acc[0][0] = ffma2(A0, B0, acc[0][0]); acc[0][1] = ffma2(A0, B1, acc[0][1]);
            acc[1][0] = ffma2(A1, B0, acc[1][0]); acc[1][1] = ffma2(A1, B1, acc[1][1]);
            acc[2][0] = ffma2(A2, B0, acc[2][0]); acc[2][1] = ffma2(A2, B1, acc[2][1]);
            acc[3][0] = ffma2(A3, B0, acc[3][0]); acc[3][1] = ffma2(A3, B1, acc[3][1]);
        }
    };

    prefetch(0);
    for (int it = 0; it < 1024; ++it) {            // 64 k-tiles * 2 phases * 8 d-chunks
        __syncthreads();
        // stage A (duplicated) and B (dd-major)
        sm.t.A[lr][lc + 0] = make_float2(pa0.x, pa0.x);
        sm.t.A[lr][lc + 1] = make_float2(pa0.y, pa0.y);
        sm.t.A[lr][lc + 2] = make_float2(pa0.z, pa0.z);
        sm.t.A[lr][lc + 3] = make_float2(pa0.w, pa0.w);
        sm.t.A[lr][lc + 4] = make_float2(pa1.x, pa1.x);
        sm.t.A[lr][lc + 5] = make_float2(pa1.y, pa1.y);
        sm.t.A[lr][lc + 6] = make_float2(pa1.z, pa1.z);
        sm.t.A[lr][lc + 7] = make_float2(pa1.w, pa1.w);
        sm.t.B[lc + 0][lr] = pb0.x;
        sm.t.B[lc + 1][lr] = pb0.y;
        sm.t.B[lc + 2][lr] = pb0.z;
        sm.t.B[lc + 3][lr] = pb0.w;
        sm.t.B[lc + 4][lr] = pb1.x;
        sm.t.B[lc + 5][lr] = pb1.y;
        sm.t.B[lc + 6][lr] = pb1.z;
        sm.t.B[lc + 7][lr] = pb1.w;
        __syncthreads();
        if (it != 1023) prefetch(it + 1);

        if (((it >> 3) & 1) == 0) compute_phase(acck);
        else                      compute_phase(accg);

        if ((it & 15) == 15) {
            int k0 = kbase + (it >> 4) * 64;
#pragma unroll
            for (int p = 0; p < 2; ++p) {
                int kA = k0 + tx * 4 + p * 2;
                float bkA = g_bkd[kA],     bgA = g_bgan[kA];
                float bkB = g_bkd[kA + 1], bgB = g_bgan[kA + 1];
#pragma unroll
                for (int i = 0; i < 4; ++i) {
                    float cklo, ckhi, cglo, cghi;
                    upk(acck[i][p], cklo, ckhi);
                    upk(accg[i][p], cglo, cghi);
                    // (a+b) - 2c : matches reference rounding (2c is exact)
                    float dkA = (ak[i] + bkA) - 2.f * cklo;
                    float dgA = (ag[i] + bgA) - 2.f * cglo;
                    Skd[i]  = fmaf(dkA, dkA, Skd[i]);
                    Sgan[i] = fmaf(dgA, dgA, Sgan[i]);
                    float dA = dkA + dgA;
                    if (dA < bestv[i]) { bestv[i] = dA; besti[i] = kA; }
                    float dkB = (ak[i] + bkB) - 2.f * ckhi;
                    float dgB = (ag[i] + bgB) - 2.f * cghi;
                    Skd[i]  = fmaf(dkB, dkB, Skd[i]);
                    Sgan[i] = fmaf(dgB, dgB, Sgan[i]);
                    float dB = dkB + dgB;
                    if (dB < bestv[i]) { bestv[i] = dB; besti[i] = kA + 1; }
                    acck[i][p] = 0ull; accg[i][p] = 0ull;
                }
            }
        }
    }

    // CTA reduction across tx (16 partials per row)
    __syncthreads();
#pragma unroll
    for (int i = 0; i < 4; ++i) {
        sm.r.S1[ty4 + i][tx] = Skd[i];
        sm.r.S2[ty4 + i][tx] = Sgan[i];
        sm.r.Bv[ty4 + i][tx] = bestv[i];
        sm.r.Bi[ty4 + i][tx] = besti[i];
    }
    __syncthreads();
    if (tid < 64) {
        float s1 = 0.f, s2 = 0.f, bv = 3.402823466e38f; int bi = 0;
#pragma unroll
        for (int e = 0; e < 16; ++e) {
            s1 += sm.r.S1[tid][e];
            s2 += sm.r.S2[tid][e];
            float v = sm.r.Bv[tid][e]; int ii = sm.r.Bi[tid][e];
            if (v < bv || (v == bv && ii < bi)) { bv = v; bi = ii; }
        }
        int n = row0 + tid;
        g_pSkd[split][n] = s1;
        g_pSgan[split][n] = s2;
        g_pBv[split][n] = bv;
        g_pBi[split][n] = bi;
    }
}

// ---------------- 6. combine splits, emit idx ----------------
__global__ void k_combine(float* __restrict__ out) {
    int n = blockIdx.x * 256 + threadIdx.x;
    float v0 = g_pBv[0][n], v1 = g_pBv[1][n];
    int idx = (v1 < v0) ? g_pBi[1][n] : g_pBi[0][n];   // tie -> split 0 (smaller k)
    g_idx[n] = idx;
    out[NQ + 2 + n] = (float)idx;
}

// ---------------- 7. scalar reductions ----------------
__global__ void k_scalar(float* __restrict__ out) {
    __shared__ float r1[256], r2[256];
    int t = threadIdx.x;
    float s1 = 0.f, s2 = 0.f;
    for (int m = 0; m < 32; ++m) {
        int n = t + m * 256;
        s1 += g_pSkd[0][n] + g_pSkd[1][n];
        s2 += g_pSgan[0][n] + g_pSgan[1][n];
    }
    r1[t] = s1; r2[t] = s2;
    __syncthreads();
    for (int s = 128; s > 0; s >>= 1) {
        if (t < s) { r1[t] += r1[t + s]; r2[t] += r2[t + s]; }
        __syncthreads();
    }
    if (t == 0) {
        out[NQ]     = r1[0] * (1.f / 8192.f);
        out[NQ + 1] = r2[0] * (1.f / 8192.f);
    }
}

// ---------------- 8. z_q gather (STE rounding replicated exactly) ----------------
__global__ void k_zq(float* __restrict__ out) {
    int row0 = blockIdx.x * 64;          // 128 blocks
    int b  = row0 >> 10;
    int l0 = row0 & 1023;
    int lq = threadIdx.x & 63;
    int dg = threadIdx.x >> 6;           // 0..3
    int n  = row0 + lq;
    int kidx = g_idx[n];
    const float* Erow = g_En + (size_t)kidx * EDIM;
    const float* Zrow = g_Zn + (size_t)n * EDIM;
#pragma unroll 4
    for (int dit = 0; dit < 128; ++dit) {
        int d = dg * 128 + dit;
        float ev = Erow[d];
        float zn = Zrow[d];
        out[((size_t)b * D_ + d) * L_ + l0 + lq] = zn + (ev - zn);
    }
}

// ---------------- launch ----------------
extern "C" void kernel_launch(void* const* d_in, const int* in_sizes, int n_in,
                              void* d_out, int out_size) {
    (void)in_sizes; (void)n_in; (void)out_size;
    const float* z    = (const float*)d_in[0];
    const float* ekd  = (const float*)d_in[1];
    const float* egan = (const float*)d_in[2];
    float* out = (float*)d_out;

    k_emb<<<KCB / 8, 256>>>(ekd, egan);
    k_zsumsq<<<dim3(4, 8, 8), 256>>>(z);
    k_zfinal<<<NPOS / 256, 256>>>();
    k_ztrans<<<dim3(16, 32, 8), dim3(32, 8)>>>(z);
    k_gemm<<<dim3(128, 2), 256>>>();
    k_combine<<<NPOS / 256, 256>>>(out);
    k_scalar<<<1, 256>>>(out);
    k_zq<<<128, 256>>>(out);
}